// round 12
// baseline (speedup 1.0000x reference)
#include <cuda_runtime.h>
#include <cuda_bf16.h>
#include <cstdint>

#define NODE_DIM 256
#define HIDDEN   128
#define MAX_NODES 100000

// ---------------- device scratch ----------------
__device__ float         g_PQ [(size_t)MAX_NODES * 256];   // P(+b1)|Q per node
__device__ __nv_bfloat16 g_Bhi[256 * 256];                  // B[n][k] = W1ab[k][n]
__device__ __nv_bfloat16 g_Blo[256 * 256];

// ---------------- helpers ----------------
__device__ __forceinline__ uint32_t smem_u32(const void* p) {
    uint32_t a;
    asm("{ .reg .u64 t; cvta.to.shared.u64 t, %1; cvt.u32.u64 %0, t; }" : "=r"(a) : "l"(p));
    return a;
}
__device__ __forceinline__ void ldsm4(uint32_t* r, uint32_t addr) {
    asm volatile("ldmatrix.sync.aligned.m8n8.x4.shared.b16 {%0,%1,%2,%3}, [%4];"
        : "=r"(r[0]), "=r"(r[1]), "=r"(r[2]), "=r"(r[3]) : "r"(addr));
}
__device__ __forceinline__ void mma_bf16(float* d, const uint32_t* a, const uint32_t* b) {
    asm volatile("mma.sync.aligned.m16n8k16.row.col.f32.bf16.bf16.f32 "
        "{%0,%1,%2,%3}, {%4,%5,%6,%7}, {%8,%9}, {%0,%1,%2,%3};"
        : "+f"(d[0]), "+f"(d[1]), "+f"(d[2]), "+f"(d[3])
        : "r"(a[0]), "r"(a[1]), "r"(a[2]), "r"(a[3]), "r"(b[0]), "r"(b[1]));
}
#define SW128(o) ((o) ^ (((o) >> 3) & 0x70))

union BP4 { __nv_bfloat16 b[4]; uint2 u; };
__device__ __forceinline__ void split4(const float4& v, uint2& uh, uint2& ul) {
    float x[4] = {v.x, v.y, v.z, v.w};
    BP4 hi, lo;
    #pragma unroll
    for (int t = 0; t < 4; t++) {
        hi.b[t] = __float2bfloat16(x[t]);
        lo.b[t] = __float2bfloat16(x[t] - __bfloat162float(hi.b[t]));
    }
    uh = hi.u; ul = lo.u;
}

// ---------------------------------------------------------------------------
// conv_B: B[n][k] bf16 hi/lo.  n<128 -> W1[k][n]; n>=128 -> W1[256+k][n-128]
// ---------------------------------------------------------------------------
__global__ void conv_B_kernel(const float* __restrict__ W1) {
    int idx = blockIdx.x * blockDim.x + threadIdx.x;   // 0..65535
    int n = idx >> 8, k = idx & 255;
    float w = (n < HIDDEN) ? W1[(size_t)k * HIDDEN + n]
                           : W1[(size_t)(256 + k) * HIDDEN + (n - HIDDEN)];
    __nv_bfloat16 hi = __float2bfloat16(w);
    __nv_bfloat16 lo = __float2bfloat16(w - __bfloat162float(hi));
    g_Bhi[idx] = hi;
    g_Blo[idx] = lo;
}

// ---------------------------------------------------------------------------
// Phase 1 (unchanged from R11): PQ = z @ [W1a|W1b], mma.sync bf16 3-term,
// fused z convert, 4x4 warp tiling, b1 folded into P half.
// ---------------------------------------------------------------------------
#define SA_HI 0
#define SA_LO 16384
#define SB_HI 32768
#define SB_LO 65536
#define GSMEM 98304

__global__ __launch_bounds__(512, 1) void gemm_tc_kernel(
    const float* __restrict__ z, const float* __restrict__ b1, int M)
{
    extern __shared__ char smem[];
    const uint32_t sb = smem_u32(smem);
    const int tid  = threadIdx.x;
    const int warp = tid >> 5;
    const int lane = tid & 31;
    const int wr   = warp & 3;
    const int wc   = warp >> 2;
    const int m0   = blockIdx.x * 128;

    const uint32_t a_rbase = wr * 32 + ((lane >> 3) & 1) * 8 + (lane & 7);
    const uint32_t a_koff  = (lane >> 4) * 16;
    const uint32_t b_rowi  = ((lane >> 4) & 1) * 8 + (lane & 7);
    const uint32_t b_koff  = ((lane >> 3) & 1) * 16;

    float acc[2][8][4];
    #pragma unroll
    for (int mt = 0; mt < 2; mt++)
        #pragma unroll
        for (int i = 0; i < 8; i++)
            #pragma unroll
            for (int j = 0; j < 4; j++) acc[mt][i][j] = 0.f;

    #pragma unroll 1
    for (int ch = 0; ch < 4; ch++) {
        const int kc = ch * 64;
        __syncthreads();
        #pragma unroll
        for (int j = 0; j < 4; j++) {
            int id = j * 512 + tid;
            int r = id >> 4, c = id & 15;
            float4 v = make_float4(0.f, 0.f, 0.f, 0.f);
            if (m0 + r < M)
                v = *(const float4*)(z + (size_t)(m0 + r) * 256 + kc + c * 4);
            uint2 uh, ul;
            split4(v, uh, ul);
            uint32_t so = SW128((uint32_t)(r * 128 + c * 8));
            *(uint2*)(smem + SA_HI + so) = uh;
            *(uint2*)(smem + SA_LO + so) = ul;
        }
        #pragma unroll
        for (int j = 0; j < 4; j++) {
            int id = j * 512 + tid;
            int r = id >> 3, c = id & 7;
            size_t off = (size_t)r * 256 + kc + c * 8;
            uint4 vh = *(const uint4*)(g_Bhi + off);
            uint4 vl = *(const uint4*)(g_Blo + off);
            uint32_t so = SW128((uint32_t)(r * 128 + c * 16));
            *(uint4*)(smem + SB_HI + so) = vh;
            *(uint4*)(smem + SB_LO + so) = vl;
        }
        __syncthreads();

        #pragma unroll
        for (int kt = 0; kt < 4; kt++) {
            uint32_t ah[2][4], al[2][4];
            #pragma unroll
            for (int mt = 0; mt < 2; mt++) {
                uint32_t aoff = SW128((a_rbase + mt * 16) * 128 + kt * 32 + a_koff);
                ldsm4(ah[mt], sb + SA_HI + aoff);
                ldsm4(al[mt], sb + SA_LO + aoff);
            }
            #pragma unroll
            for (int bg = 0; bg < 4; bg++) {
                uint32_t boff = SW128((uint32_t)((wc * 64 + bg * 16 + b_rowi) * 128
                                                 + kt * 32 + b_koff));
                uint32_t bh[4], bl[4];
                ldsm4(bh, sb + SB_HI + boff);
                ldsm4(bl, sb + SB_LO + boff);
                #pragma unroll
                for (int mt = 0; mt < 2; mt++) {
                    mma_bf16(acc[mt][2 * bg],     ah[mt], bh);
                    mma_bf16(acc[mt][2 * bg],     ah[mt], bl);
                    mma_bf16(acc[mt][2 * bg],     al[mt], bh);
                    mma_bf16(acc[mt][2 * bg + 1], ah[mt], bh + 2);
                    mma_bf16(acc[mt][2 * bg + 1], ah[mt], bl + 2);
                    mma_bf16(acc[mt][2 * bg + 1], al[mt], bh + 2);
                }
            }
        }
    }

    const int cbl = 2 * (lane & 3);
    #pragma unroll
    for (int mt = 0; mt < 2; mt++) {
        const int r0 = m0 + wr * 32 + mt * 16 + (lane >> 2);
        #pragma unroll
        for (int nn = 0; nn < 8; nn++) {
            int n0 = wc * 64 + nn * 8 + cbl;
            float2 bb = make_float2(0.f, 0.f);
            if (n0 < 128) bb = __ldg((const float2*)(b1 + n0));
            if (r0 < M)
                *(float2*)(g_PQ + (size_t)r0 * 256 + n0) =
                    make_float2(acc[mt][nn][0] + bb.x, acc[mt][nn][1] + bb.y);
            if (r0 + 8 < M)
                *(float2*)(g_PQ + (size_t)(r0 + 8) * 256 + n0) =
                    make_float2(acc[mt][nn][2] + bb.x, acc[mt][nn][3] + bb.y);
        }
    }
}

// ---------------------------------------------------------------------------
// Phase 2: barrier-free warp pipeline + TRANSPOSED epilogue:
// acc -> warp-private smem [16 edges][132], then 4 lane-octets gather one
// edge-line (128B) per LDG.128 instruction (minimal L1 wavefronts).
// ---------------------------------------------------------------------------
#define ES_AH   0
#define ES_AL   10240
#define ES_WH   20480
#define ES_WL   30720
#define ES_W2   40960
#define ES_T    41472                      // 8 warps x 16 x 132 floats
#define ESMEM   (41472 + 67584)            // 109056

__global__ __launch_bounds__(256, 2) void edge_kernel(
    const int* __restrict__ eli, const float* __restrict__ ea,
    const float* __restrict__ W1, const float* __restrict__ W2,
    const float* __restrict__ b2, float* __restrict__ out, int E)
{
    extern __shared__ char es[];
    __nv_bfloat16* sAh = (__nv_bfloat16*)(es + ES_AH);
    __nv_bfloat16* sAl = (__nv_bfloat16*)(es + ES_AL);
    __nv_bfloat16* sWh = (__nv_bfloat16*)(es + ES_WH);
    __nv_bfloat16* sWl = (__nv_bfloat16*)(es + ES_WL);
    float*         sW2 = (float*)(es + ES_W2);
    float*         sT  = (float*)(es + ES_T);

    const int tid  = threadIdx.x;
    const int warp = tid >> 5;
    const int lane = tid & 31;

    // One-time: W1c -> sW[n][k] hi/lo (rows of 40 bf16), W2
    #pragma unroll
    for (int j = 0; j < 16; j++) {
        int id = j * 256 + tid;            // 0..4095
        int k = id >> 7, n = id & 127;
        float w = W1[(size_t)(512 + k) * HIDDEN + n];
        __nv_bfloat16 hi = __float2bfloat16(w);
        sWh[n * 40 + k] = hi;
        sWl[n * 40 + k] = __float2bfloat16(w - __bfloat162float(hi));
    }
    if (tid < 128) sW2[tid] = W2[tid];
    const float b2v = b2[0];
    __syncthreads();            // only block barrier: sW/sW2 ready

    __nv_bfloat16* wAh = sAh + warp * 640;
    __nv_bfloat16* wAl = sAl + warp * 640;
    float*         wT  = sT + warp * 2112;    // 16 x 132 floats
    const uint32_t sbAh = smem_u32(wAh), sbAl = smem_u32(wAl);
    const uint32_t sbWh = smem_u32(sWh), sbWl = smem_u32(sWl);

    const uint32_t a_row  = ((lane >> 3) & 1) * 8 + (lane & 7);   // 0..15 local
    const uint32_t a_koff = (lane >> 4) * 16;
    const uint32_t b_rowi = ((lane >> 4) & 1) * 8 + (lane & 7);
    const uint32_t b_koff = ((lane >> 3) & 1) * 16;
    const int rloc = lane >> 2;
    const int cb   = 2 * (lane & 3);
    const int g    = lane >> 3;          // octet id 0..3
    const int o    = lane & 7;           // lane within octet

    // W2 fragments for this lane's gather columns (cols t*32 + 4o .. +3)
    float4 w2reg[4];
    #pragma unroll
    for (int t = 0; t < 4; t++)
        w2reg[t] = *(const float4*)(sW2 + t * 32 + 4 * o);

    const int ntiles = (E + 15) / 16;
    const int gw     = blockIdx.x * 8 + warp;
    const int nwarps = gridDim.x * 8;

    for (int t0 = gw; t0 < ntiles; t0 += nwarps) {
        const int e0 = t0 * 16;

        int e_ld = e0 + (lane & 15);
        int idxv = 0;
        if (e_ld < E) idxv = (lane < 16) ? eli[e_ld] : eli[(size_t)E + e_ld];

        // EA: 16 rows x 32 floats -> bf16 hi/lo, rows of 40
        #pragma unroll
        for (int jj = 0; jj < 4; jj++) {
            int id = jj * 32 + lane;        // 0..127 float4 slots
            int r = id >> 3, c4 = id & 7;
            float4 v = make_float4(0.f, 0.f, 0.f, 0.f);
            if (e0 + r < E)
                v = *(const float4*)(ea + (size_t)e0 * 32 + id * 4);
            uint2 uh, ul;
            split4(v, uh, ul);
            *(uint2*)(wAh + r * 40 + c4 * 4) = uh;
            *(uint2*)(wAl + r * 40 + c4 * 4) = ul;
        }
        __syncwarp();

        // MMA: D[16e x 128n] = EA @ W1c, 3-term split
        float acc[16][4];
        #pragma unroll
        for (int i = 0; i < 16; i++)
            #pragma unroll
            for (int j = 0; j < 4; j++) acc[i][j] = 0.f;

        #pragma unroll
        for (int kt = 0; kt < 2; kt++) {
            uint32_t ah[4], al[4];
            uint32_t aoff = a_row * 80 + kt * 32 + a_koff;
            ldsm4(ah, sbAh + aoff);
            ldsm4(al, sbAl + aoff);
            #pragma unroll
            for (int ntp = 0; ntp < 8; ntp++) {
                uint32_t boff = (ntp * 16 + b_rowi) * 80 + kt * 32 + b_koff;
                uint32_t bh[4], bl[4];
                ldsm4(bh, sbWh + boff);
                ldsm4(bl, sbWl + boff);
                mma_bf16(acc[2 * ntp],     ah, bh);
                mma_bf16(acc[2 * ntp],     ah, bl);
                mma_bf16(acc[2 * ntp],     al, bh);
                mma_bf16(acc[2 * ntp + 1], ah, bh + 2);
                mma_bf16(acc[2 * ntp + 1], ah, bl + 2);
                mma_bf16(acc[2 * ntp + 1], al, bh + 2);
            }
        }
        __syncwarp();   // wAh/wAl consumed

        // Transpose acc into wT[edge][col] (warp-private)
        #pragma unroll
        for (int nt = 0; nt < 16; nt++) {
            *(float2*)(wT + rloc * 132 + nt * 8 + cb) =
                make_float2(acc[nt][0], acc[nt][1]);
            *(float2*)(wT + (rloc + 8) * 132 + nt * 8 + cb) =
                make_float2(acc[nt][2], acc[nt][3]);
        }
        __syncwarp();

        // Gather: octet g handles edge j = jj*4 + g; lane o covers cols t*32+4o
        #pragma unroll 2
        for (int jj = 0; jj < 4; jj++) {
            int j = jj * 4 + g;
            int e = e0 + j;
            int s = __shfl_sync(0xffffffffu, idxv, j);
            int d = __shfl_sync(0xffffffffu, idxv, j + 16);
            const float* pb = g_PQ + (size_t)s * 256 + 4 * o;
            const float* qb = g_PQ + (size_t)d * 256 + 128 + 4 * o;
            const float* ab = wT + j * 132 + 4 * o;
            float part = 0.f;
            #pragma unroll
            for (int t = 0; t < 4; t++) {
                float4 p4 = __ldg((const float4*)(pb + t * 32));
                float4 q4 = __ldg((const float4*)(qb + t * 32));
                float4 a4 = *(const float4*)(ab + t * 32);
                float h0 = fmaxf(a4.x + p4.x + q4.x, 0.f);
                float h1 = fmaxf(a4.y + p4.y + q4.y, 0.f);
                float h2 = fmaxf(a4.z + p4.z + q4.z, 0.f);
                float h3 = fmaxf(a4.w + p4.w + q4.w, 0.f);
                part = fmaf(h0, w2reg[t].x, fmaf(h1, w2reg[t].y,
                       fmaf(h2, w2reg[t].z, fmaf(h3, w2reg[t].w, part))));
            }
            part += __shfl_xor_sync(0xffffffffu, part, 1);
            part += __shfl_xor_sync(0xffffffffu, part, 2);
            part += __shfl_xor_sync(0xffffffffu, part, 4);
            if (o == 0 && e < E)
                out[e] = part + b2v;
        }
        __syncwarp();   // wT consumed; safe to overwrite next tile
    }
}

// ---------------------------------------------------------------------------
extern "C" void kernel_launch(void* const* d_in, const int* in_sizes, int n_in,
                              void* d_out, int out_size) {
    const float* z   = (const float*)d_in[0];
    const int*   eli = (const int*)d_in[1];      // int32 (JAX canonicalized)
    const float* ea  = (const float*)d_in[2];
    const float* W1  = (const float*)d_in[3];
    const float* b1  = (const float*)d_in[4];
    const float* W2  = (const float*)d_in[5];
    const float* b2  = (const float*)d_in[6];
    float* out = (float*)d_out;

    int M = in_sizes[0] / NODE_DIM;   // 100000
    int E = out_size;                 // 1000000

    cudaFuncSetAttribute(gemm_tc_kernel,
                         cudaFuncAttributeMaxDynamicSharedMemorySize, GSMEM);
    cudaFuncSetAttribute(edge_kernel,
                         cudaFuncAttributeMaxDynamicSharedMemorySize, ESMEM);

    conv_B_kernel<<<256, 256>>>(W1);

    int gblocks = (M + 127) / 128;
    gemm_tc_kernel<<<gblocks, 512, GSMEM>>>(z, b1, M);

    edge_kernel<<<296, 256, ESMEM>>>(eli, ea, W1, W2, b2, out, E);
}

// round 15
// speedup vs baseline: 1.4927x; 1.4927x over previous
#include <cuda_runtime.h>
#include <cuda_bf16.h>
#include <cuda_fp16.h>
#include <cstdint>

#define NODE_DIM 256
#define HIDDEN   128
#define MAX_NODES 100000

// ---------------- device scratch ----------------
__device__ __half        g_PQ [(size_t)MAX_NODES * 256];   // fp16 P(+b1)|Q per node
__device__ __nv_bfloat16 g_Bhi[256 * 256];                  // B[n][k] = W1ab[k][n]
__device__ __nv_bfloat16 g_Blo[256 * 256];

// ---------------- helpers ----------------
__device__ __forceinline__ uint32_t smem_u32(const void* p) {
    uint32_t a;
    asm("{ .reg .u64 t; cvta.to.shared.u64 t, %1; cvt.u32.u64 %0, t; }" : "=r"(a) : "l"(p));
    return a;
}
__device__ __forceinline__ void ldsm4(uint32_t* r, uint32_t addr) {
    asm volatile("ldmatrix.sync.aligned.m8n8.x4.shared.b16 {%0,%1,%2,%3}, [%4];"
        : "=r"(r[0]), "=r"(r[1]), "=r"(r[2]), "=r"(r[3]) : "r"(addr));
}
__device__ __forceinline__ void mma_bf16(float* d, const uint32_t* a, const uint32_t* b) {
    asm volatile("mma.sync.aligned.m16n8k16.row.col.f32.bf16.bf16.f32 "
        "{%0,%1,%2,%3}, {%4,%5,%6,%7}, {%8,%9}, {%0,%1,%2,%3};"
        : "+f"(d[0]), "+f"(d[1]), "+f"(d[2]), "+f"(d[3])
        : "r"(a[0]), "r"(a[1]), "r"(a[2]), "r"(a[3]), "r"(b[0]), "r"(b[1]));
}
#define SW128(o) ((o) ^ (((o) >> 3) & 0x70))

union BP4 { __nv_bfloat16 b[4]; uint2 u; };
__device__ __forceinline__ void split4(const float4& v, uint2& uh, uint2& ul) {
    float x[4] = {v.x, v.y, v.z, v.w};
    BP4 hi, lo;
    #pragma unroll
    for (int t = 0; t < 4; t++) {
        hi.b[t] = __float2bfloat16(x[t]);
        lo.b[t] = __float2bfloat16(x[t] - __bfloat162float(hi.b[t]));
    }
    uh = hi.u; ul = lo.u;
}

// ---------------------------------------------------------------------------
// conv_B: B[n][k] bf16 hi/lo.  n<128 -> W1[k][n]; n>=128 -> W1[256+k][n-128]
// ---------------------------------------------------------------------------
__global__ void conv_B_kernel(const float* __restrict__ W1) {
    int idx = blockIdx.x * blockDim.x + threadIdx.x;   // 0..65535
    int n = idx >> 8, k = idx & 255;
    float w = (n < HIDDEN) ? W1[(size_t)k * HIDDEN + n]
                           : W1[(size_t)(256 + k) * HIDDEN + (n - HIDDEN)];
    __nv_bfloat16 hi = __float2bfloat16(w);
    __nv_bfloat16 lo = __float2bfloat16(w - __bfloat162float(hi));
    g_Bhi[idx] = hi;
    g_Blo[idx] = lo;
}

// ---------------------------------------------------------------------------
// Phase 1 (R11): PQ = z @ [W1a|W1b], mma.sync bf16 3-term split, fused z
// convert, 4x4 warp tiling. b1 folded into P half; output stored as fp16.
// ---------------------------------------------------------------------------
#define SA_HI 0
#define SA_LO 16384
#define SB_HI 32768
#define SB_LO 65536
#define GSMEM 98304

__global__ __launch_bounds__(512, 1) void gemm_tc_kernel(
    const float* __restrict__ z, const float* __restrict__ b1, int M)
{
    extern __shared__ char smem[];
    const uint32_t sb = smem_u32(smem);
    const int tid  = threadIdx.x;
    const int warp = tid >> 5;
    const int lane = tid & 31;
    const int wr   = warp & 3;
    const int wc   = warp >> 2;
    const int m0   = blockIdx.x * 128;

    const uint32_t a_rbase = wr * 32 + ((lane >> 3) & 1) * 8 + (lane & 7);
    const uint32_t a_koff  = (lane >> 4) * 16;
    const uint32_t b_rowi  = ((lane >> 4) & 1) * 8 + (lane & 7);
    const uint32_t b_koff  = ((lane >> 3) & 1) * 16;

    float acc[2][8][4];
    #pragma unroll
    for (int mt = 0; mt < 2; mt++)
        #pragma unroll
        for (int i = 0; i < 8; i++)
            #pragma unroll
            for (int j = 0; j < 4; j++) acc[mt][i][j] = 0.f;

    #pragma unroll 1
    for (int ch = 0; ch < 4; ch++) {
        const int kc = ch * 64;
        __syncthreads();
        #pragma unroll
        for (int j = 0; j < 4; j++) {
            int id = j * 512 + tid;
            int r = id >> 4, c = id & 15;
            float4 v = make_float4(0.f, 0.f, 0.f, 0.f);
            if (m0 + r < M)
                v = *(const float4*)(z + (size_t)(m0 + r) * 256 + kc + c * 4);
            uint2 uh, ul;
            split4(v, uh, ul);
            uint32_t so = SW128((uint32_t)(r * 128 + c * 8));
            *(uint2*)(smem + SA_HI + so) = uh;
            *(uint2*)(smem + SA_LO + so) = ul;
        }
        #pragma unroll
        for (int j = 0; j < 4; j++) {
            int id = j * 512 + tid;
            int r = id >> 3, c = id & 7;
            size_t off = (size_t)r * 256 + kc + c * 8;
            uint4 vh = *(const uint4*)(g_Bhi + off);
            uint4 vl = *(const uint4*)(g_Blo + off);
            uint32_t so = SW128((uint32_t)(r * 128 + c * 16));
            *(uint4*)(smem + SB_HI + so) = vh;
            *(uint4*)(smem + SB_LO + so) = vl;
        }
        __syncthreads();

        #pragma unroll
        for (int kt = 0; kt < 4; kt++) {
            uint32_t ah[2][4], al[2][4];
            #pragma unroll
            for (int mt = 0; mt < 2; mt++) {
                uint32_t aoff = SW128((a_rbase + mt * 16) * 128 + kt * 32 + a_koff);
                ldsm4(ah[mt], sb + SA_HI + aoff);
                ldsm4(al[mt], sb + SA_LO + aoff);
            }
            #pragma unroll
            for (int bg = 0; bg < 4; bg++) {
                uint32_t boff = SW128((uint32_t)((wc * 64 + bg * 16 + b_rowi) * 128
                                                 + kt * 32 + b_koff));
                uint32_t bh[4], bl[4];
                ldsm4(bh, sb + SB_HI + boff);
                ldsm4(bl, sb + SB_LO + boff);
                #pragma unroll
                for (int mt = 0; mt < 2; mt++) {
                    mma_bf16(acc[mt][2 * bg],     ah[mt], bh);
                    mma_bf16(acc[mt][2 * bg],     ah[mt], bl);
                    mma_bf16(acc[mt][2 * bg],     al[mt], bh);
                    mma_bf16(acc[mt][2 * bg + 1], ah[mt], bh + 2);
                    mma_bf16(acc[mt][2 * bg + 1], ah[mt], bl + 2);
                    mma_bf16(acc[mt][2 * bg + 1], al[mt], bh + 2);
                }
            }
        }
    }

    // Epilogue: +b1 on P half (cols < 128), convert fp16, write g_PQ
    const int cbl = 2 * (lane & 3);
    #pragma unroll
    for (int mt = 0; mt < 2; mt++) {
        const int r0 = m0 + wr * 32 + mt * 16 + (lane >> 2);
        #pragma unroll
        for (int nn = 0; nn < 8; nn++) {
            int n0 = wc * 64 + nn * 8 + cbl;
            float2 bb = make_float2(0.f, 0.f);
            if (n0 < 128) bb = __ldg((const float2*)(b1 + n0));
            if (r0 < M)
                *(__half2*)(g_PQ + (size_t)r0 * 256 + n0) =
                    __floats2half2_rn(acc[mt][nn][0] + bb.x, acc[mt][nn][1] + bb.y);
            if (r0 + 8 < M)
                *(__half2*)(g_PQ + (size_t)(r0 + 8) * 256 + n0) =
                    __floats2half2_rn(acc[mt][nn][2] + bb.x, acc[mt][nn][3] + bb.y);
        }
    }
}

// ---------------------------------------------------------------------------
// Phase 2 (R11 structure): barrier-free warp-independent pipeline.
// P/Q gathers are fp16 (__half2) -> half the gather bytes, L2-resident set.
// ---------------------------------------------------------------------------
__global__ __launch_bounds__(256, 2) void edge_kernel(
    const int* __restrict__ eli, const float* __restrict__ ea,
    const float* __restrict__ W1, const float* __restrict__ W2,
    const float* __restrict__ b2, float* __restrict__ out, int E)
{
    __shared__ __align__(16) __nv_bfloat16 sAh[8 * 16 * 40];  // per-warp 16x40
    __shared__ __align__(16) __nv_bfloat16 sAl[8 * 16 * 40];
    __shared__ __align__(16) __nv_bfloat16 sWh[128 * 40];
    __shared__ __align__(16) __nv_bfloat16 sWl[128 * 40];
    __shared__ float sW2[128];

    const int tid  = threadIdx.x;
    const int warp = tid >> 5;
    const int lane = tid & 31;

    #pragma unroll
    for (int j = 0; j < 16; j++) {
        int id = j * 256 + tid;            // 0..4095
        int k = id >> 7, n = id & 127;
        float w = W1[(size_t)(512 + k) * HIDDEN + n];
        __nv_bfloat16 hi = __float2bfloat16(w);
        sWh[n * 40 + k] = hi;
        sWl[n * 40 + k] = __float2bfloat16(w - __bfloat162float(hi));
    }
    if (tid < 128) sW2[tid] = W2[tid];
    const float b2v = b2[0];
    __syncthreads();            // only barrier: sW/sW2 ready

    __nv_bfloat16* wAh = sAh + warp * 640;
    __nv_bfloat16* wAl = sAl + warp * 640;
    const uint32_t sbAh = smem_u32(wAh), sbAl = smem_u32(wAl);
    const uint32_t sbWh = smem_u32(sWh), sbWl = smem_u32(sWl);

    const uint32_t a_row  = ((lane >> 3) & 1) * 8 + (lane & 7);   // 0..15 local
    const uint32_t a_koff = (lane >> 4) * 16;
    const uint32_t b_rowi = ((lane >> 4) & 1) * 8 + (lane & 7);
    const uint32_t b_koff = ((lane >> 3) & 1) * 16;
    const int cq = lane & 3;           // quad col group

    const int ntiles = (E + 15) / 16;                 // 16-edge tiles
    const int gw     = blockIdx.x * 8 + warp;         // global warp id
    const int nwarps = gridDim.x * 8;

    for (int t = gw; t < ntiles; t += nwarps) {
        const int e0 = t * 16;

        int e_ld = e0 + (lane & 15);
        int idxv = 0;
        if (e_ld < E) idxv = (lane < 16) ? eli[e_ld] : eli[(size_t)E + e_ld];

        #pragma unroll
        for (int jj = 0; jj < 4; jj++) {
            int id = jj * 32 + lane;        // 0..127 float4 slots
            int r = id >> 3, c4 = id & 7;
            float4 v = make_float4(0.f, 0.f, 0.f, 0.f);
            if (e0 + r < E)
                v = *(const float4*)(ea + (size_t)e0 * 32 + id * 4);
            uint2 uh, ul;
            split4(v, uh, ul);
            *(uint2*)(wAh + r * 40 + c4 * 4) = uh;
            *(uint2*)(wAl + r * 40 + c4 * 4) = ul;
        }
        __syncwarp();

        float acc[16][4];
        #pragma unroll
        for (int i = 0; i < 16; i++)
            #pragma unroll
            for (int j = 0; j < 4; j++) acc[i][j] = 0.f;

        #pragma unroll
        for (int kt = 0; kt < 2; kt++) {
            uint32_t ah[4], al[4];
            uint32_t aoff = a_row * 80 + kt * 32 + a_koff;
            ldsm4(ah, sbAh + aoff);
            ldsm4(al, sbAl + aoff);
            #pragma unroll
            for (int ntp = 0; ntp < 8; ntp++) {
                uint32_t boff = (ntp * 16 + b_rowi) * 80 + kt * 32 + b_koff;
                uint32_t bh[4], bl[4];
                ldsm4(bh, sbWh + boff);
                ldsm4(bl, sbWl + boff);
                mma_bf16(acc[2 * ntp],     ah, bh);
                mma_bf16(acc[2 * ntp],     ah, bl);
                mma_bf16(acc[2 * ntp],     al, bh);
                mma_bf16(acc[2 * ntp + 1], ah, bh + 2);
                mma_bf16(acc[2 * ntp + 1], ah, bl + 2);
                mma_bf16(acc[2 * ntp + 1], al, bh + 2);
            }
        }
        __syncwarp();

        #pragma unroll
        for (int i = 0; i < 2; i++) {
            int j    = (lane >> 2) + 8 * i;           // local edge 0..15
            int e    = e0 + j;
            int s    = __shfl_sync(0xffffffffu, idxv, j);
            int d    = __shfl_sync(0xffffffffu, idxv, j + 16);
            const __half2* pb = (const __half2*)(g_PQ + (size_t)s * 256) + cq;
            const __half2* qb = (const __half2*)(g_PQ + (size_t)d * 256 + 128) + cq;
            float part = 0.f;
            #pragma unroll
            for (int nt = 0; nt < 16; nt++) {
                float2 p  = __half22float2(__ldg(pb + nt * 4));
                float2 q  = __half22float2(__ldg(qb + nt * 4));
                float2 w2 = *(const float2*)(&sW2[nt * 8 + 2 * cq]);
                float h0 = fmaxf(acc[nt][2 * i]     + p.x + q.x, 0.f);
                float h1 = fmaxf(acc[nt][2 * i + 1] + p.y + q.y, 0.f);
                part = fmaf(h0, w2.x, fmaf(h1, w2.y, part));
            }
            part += __shfl_xor_sync(0xffffffffu, part, 1);
            part += __shfl_xor_sync(0xffffffffu, part, 2);
            if ((lane & 3) == 0 && e < E)
                out[e] = part + b2v;
        }
    }
}

// ---------------------------------------------------------------------------
extern "C" void kernel_launch(void* const* d_in, const int* in_sizes, int n_in,
                              void* d_out, int out_size) {
    const float* z   = (const float*)d_in[0];
    const int*   eli = (const int*)d_in[1];      // int32 (JAX canonicalized)
    const float* ea  = (const float*)d_in[2];
    const float* W1  = (const float*)d_in[3];
    const float* b1  = (const float*)d_in[4];
    const float* W2  = (const float*)d_in[5];
    const float* b2  = (const float*)d_in[6];
    float* out = (float*)d_out;

    int M = in_sizes[0] / NODE_DIM;   // 100000
    int E = out_size;                 // 1000000

    cudaFuncSetAttribute(gemm_tc_kernel,
                         cudaFuncAttributeMaxDynamicSharedMemorySize, GSMEM);

    conv_B_kernel<<<256, 256>>>(W1);

    int gblocks = (M + 127) / 128;
    gemm_tc_kernel<<<gblocks, 512, GSMEM>>>(z, b1, M);

    edge_kernel<<<296, 256>>>(eli, ea, W1, W2, b2, out, E);
}

// round 16
// speedup vs baseline: 1.5147x; 1.0148x over previous
#include <cuda_runtime.h>
#include <cuda_bf16.h>
#include <cuda_fp16.h>
#include <cstdint>

#define NODE_DIM 256
#define HIDDEN   128
#define MAX_NODES 100000

// ---------------- device scratch ----------------
__device__ __half        g_PQ [(size_t)MAX_NODES * 256];   // fp16 P(+b1)|Q per node
__device__ __nv_bfloat16 g_Bhi[256 * 256];                  // B[n][k] = W1ab[k][n]
__device__ __nv_bfloat16 g_Blo[256 * 256];

// ---------------- helpers ----------------
__device__ __forceinline__ uint32_t smem_u32(const void* p) {
    uint32_t a;
    asm("{ .reg .u64 t; cvta.to.shared.u64 t, %1; cvt.u32.u64 %0, t; }" : "=r"(a) : "l"(p));
    return a;
}
__device__ __forceinline__ void ldsm4(uint32_t* r, uint32_t addr) {
    asm volatile("ldmatrix.sync.aligned.m8n8.x4.shared.b16 {%0,%1,%2,%3}, [%4];"
        : "=r"(r[0]), "=r"(r[1]), "=r"(r[2]), "=r"(r[3]) : "r"(addr));
}
__device__ __forceinline__ void mma_bf16(float* d, const uint32_t* a, const uint32_t* b) {
    asm volatile("mma.sync.aligned.m16n8k16.row.col.f32.bf16.bf16.f32 "
        "{%0,%1,%2,%3}, {%4,%5,%6,%7}, {%8,%9}, {%0,%1,%2,%3};"
        : "+f"(d[0]), "+f"(d[1]), "+f"(d[2]), "+f"(d[3])
        : "r"(a[0]), "r"(a[1]), "r"(a[2]), "r"(a[3]), "r"(b[0]), "r"(b[1]));
}
#define SW64S(o) ((o) ^ (((o) >> 3) & 0x30))

union BP4 { __nv_bfloat16 b[4]; uint2 u; };
__device__ __forceinline__ void split4(const float4& v, uint2& uh, uint2& ul) {
    float x[4] = {v.x, v.y, v.z, v.w};
    BP4 hi, lo;
    #pragma unroll
    for (int t = 0; t < 4; t++) {
        hi.b[t] = __float2bfloat16(x[t]);
        lo.b[t] = __float2bfloat16(x[t] - __bfloat162float(hi.b[t]));
    }
    uh = hi.u; ul = lo.u;
}

// ---------------------------------------------------------------------------
// conv_B: B[n][k] bf16 hi/lo.  n<128 -> W1[k][n]; n>=128 -> W1[256+k][n-128]
// ---------------------------------------------------------------------------
__global__ void conv_B_kernel(const float* __restrict__ W1) {
    int idx = blockIdx.x * blockDim.x + threadIdx.x;   // 0..65535
    int n = idx >> 8, k = idx & 255;
    float w = (n < HIDDEN) ? W1[(size_t)k * HIDDEN + n]
                           : W1[(size_t)(256 + k) * HIDDEN + (n - HIDDEN)];
    __nv_bfloat16 hi = __float2bfloat16(w);
    __nv_bfloat16 lo = __float2bfloat16(w - __bfloat162float(hi));
    g_Bhi[idx] = hi;
    g_Blo[idx] = lo;
}

// ---------------------------------------------------------------------------
// Phase 1 v2: PQ = z @ [W1a|W1b], mma.sync bf16 3-term split, fused z convert.
// CTA = 64 rows x 256 cols, 256 threads, 2 CTAs/SM (latency overlap).
// K-chunks of 32, SW64 swizzle (64B rows). b1 folded into P half; fp16 out.
// ---------------------------------------------------------------------------
#define SA_HI 0
#define SA_LO 4096
#define SB_HI 8192
#define SB_LO 24576
#define GSMEM 40960

__global__ __launch_bounds__(256, 2) void gemm_tc_kernel(
    const float* __restrict__ z, const float* __restrict__ b1, int M)
{
    extern __shared__ char smem[];
    const uint32_t sb = smem_u32(smem);
    const int tid  = threadIdx.x;
    const int warp = tid >> 5;
    const int lane = tid & 31;
    const int wr   = warp & 1;            // row group (32 rows)
    const int wc   = warp >> 1;           // col group (64 cols)
    const int m0   = blockIdx.x * 64;

    const uint32_t a_rbase = wr * 32 + ((lane >> 3) & 1) * 8 + (lane & 7);
    const uint32_t a_koff  = (lane >> 4) * 16;
    const uint32_t b_rowi  = ((lane >> 4) & 1) * 8 + (lane & 7);
    const uint32_t b_koff  = ((lane >> 3) & 1) * 16;

    float acc[2][8][4];
    #pragma unroll
    for (int mt = 0; mt < 2; mt++)
        #pragma unroll
        for (int i = 0; i < 8; i++)
            #pragma unroll
            for (int j = 0; j < 4; j++) acc[mt][i][j] = 0.f;

    const int lr = tid >> 2;              // 0..63 (A row)
    const int lc = tid & 3;               // 16B chunk in 64B row

    #pragma unroll 1
    for (int ch = 0; ch < 8; ch++) {
        const int kc = ch * 32;
        __syncthreads();
        // A: z fp32 (64 x 32) -> bf16 hi/lo, SW64 rows of 64B
        {
            float4 v0 = make_float4(0.f, 0.f, 0.f, 0.f), v1 = v0;
            if (m0 + lr < M) {
                const float* zp = z + (size_t)(m0 + lr) * 256 + kc + lc * 8;
                v0 = *(const float4*)zp;
                v1 = *(const float4*)(zp + 4);
            }
            uint2 h0, l0, h1, l1;
            split4(v0, h0, l0);
            split4(v1, h1, l1);
            uint32_t so = SW64S((uint32_t)(lr * 64 + lc * 16));
            *(uint4*)(smem + SA_HI + so) = make_uint4(h0.x, h0.y, h1.x, h1.y);
            *(uint4*)(smem + SA_LO + so) = make_uint4(l0.x, l0.y, l1.x, l1.y);
        }
        // B: 256 n-rows x 32 k bf16 hi/lo (from g_Bhi/g_Blo, k contiguous)
        #pragma unroll
        for (int j = 0; j < 4; j++) {
            int id = j * 256 + tid;        // 0..1023 16B granules
            int r = id >> 2, c = id & 3;
            size_t off = (size_t)r * 256 + kc + c * 8;
            uint4 vh = *(const uint4*)(g_Bhi + off);
            uint4 vl = *(const uint4*)(g_Blo + off);
            uint32_t so = SW64S((uint32_t)(r * 64 + c * 16));
            *(uint4*)(smem + SB_HI + so) = vh;
            *(uint4*)(smem + SB_LO + so) = vl;
        }
        __syncthreads();

        #pragma unroll
        for (int kt = 0; kt < 2; kt++) {
            uint32_t ah[2][4], al[2][4];
            #pragma unroll
            for (int mt = 0; mt < 2; mt++) {
                uint32_t aoff = SW64S((a_rbase + mt * 16) * 64 + kt * 32 + a_koff);
                ldsm4(ah[mt], sb + SA_HI + aoff);
                ldsm4(al[mt], sb + SA_LO + aoff);
            }
            #pragma unroll
            for (int bg = 0; bg < 4; bg++) {
                uint32_t boff = SW64S((uint32_t)((wc * 64 + bg * 16 + b_rowi) * 64
                                                 + kt * 32 + b_koff));
                uint32_t bh[4], bl[4];
                ldsm4(bh, sb + SB_HI + boff);
                ldsm4(bl, sb + SB_LO + boff);
                #pragma unroll
                for (int mt = 0; mt < 2; mt++) {
                    mma_bf16(acc[mt][2 * bg],     ah[mt], bh);
                    mma_bf16(acc[mt][2 * bg],     ah[mt], bl);
                    mma_bf16(acc[mt][2 * bg],     al[mt], bh);
                    mma_bf16(acc[mt][2 * bg + 1], ah[mt], bh + 2);
                    mma_bf16(acc[mt][2 * bg + 1], ah[mt], bl + 2);
                    mma_bf16(acc[mt][2 * bg + 1], al[mt], bh + 2);
                }
            }
        }
    }

    // Epilogue: +b1 on P half (cols < 128), convert fp16, write g_PQ
    const int cbl = 2 * (lane & 3);
    #pragma unroll
    for (int mt = 0; mt < 2; mt++) {
        const int r0 = m0 + wr * 32 + mt * 16 + (lane >> 2);
        #pragma unroll
        for (int nn = 0; nn < 8; nn++) {
            int n0 = wc * 64 + nn * 8 + cbl;
            float2 bb = make_float2(0.f, 0.f);
            if (n0 < 128) bb = __ldg((const float2*)(b1 + n0));
            if (r0 < M)
                *(__half2*)(g_PQ + (size_t)r0 * 256 + n0) =
                    __floats2half2_rn(acc[mt][nn][0] + bb.x, acc[mt][nn][1] + bb.y);
            if (r0 + 8 < M)
                *(__half2*)(g_PQ + (size_t)(r0 + 8) * 256 + n0) =
                    __floats2half2_rn(acc[mt][nn][2] + bb.x, acc[mt][nn][3] + bb.y);
        }
    }
}

// ---------------------------------------------------------------------------
// Phase 2 (unchanged from R15): barrier-free warp-independent pipeline,
// fp16 P/Q gathers.
// ---------------------------------------------------------------------------
__global__ __launch_bounds__(256, 2) void edge_kernel(
    const int* __restrict__ eli, const float* __restrict__ ea,
    const float* __restrict__ W1, const float* __restrict__ W2,
    const float* __restrict__ b2, float* __restrict__ out, int E)
{
    __shared__ __align__(16) __nv_bfloat16 sAh[8 * 16 * 40];  // per-warp 16x40
    __shared__ __align__(16) __nv_bfloat16 sAl[8 * 16 * 40];
    __shared__ __align__(16) __nv_bfloat16 sWh[128 * 40];
    __shared__ __align__(16) __nv_bfloat16 sWl[128 * 40];
    __shared__ float sW2[128];

    const int tid  = threadIdx.x;
    const int warp = tid >> 5;
    const int lane = tid & 31;

    #pragma unroll
    for (int j = 0; j < 16; j++) {
        int id = j * 256 + tid;            // 0..4095
        int k = id >> 7, n = id & 127;
        float w = W1[(size_t)(512 + k) * HIDDEN + n];
        __nv_bfloat16 hi = __float2bfloat16(w);
        sWh[n * 40 + k] = hi;
        sWl[n * 40 + k] = __float2bfloat16(w - __bfloat162float(hi));
    }
    if (tid < 128) sW2[tid] = W2[tid];
    const float b2v = b2[0];
    __syncthreads();            // only barrier: sW/sW2 ready

    __nv_bfloat16* wAh = sAh + warp * 640;
    __nv_bfloat16* wAl = sAl + warp * 640;
    const uint32_t sbAh = smem_u32(wAh), sbAl = smem_u32(wAl);
    const uint32_t sbWh = smem_u32(sWh), sbWl = smem_u32(sWl);

    const uint32_t a_row  = ((lane >> 3) & 1) * 8 + (lane & 7);   // 0..15 local
    const uint32_t a_koff = (lane >> 4) * 16;
    const uint32_t b_rowi = ((lane >> 4) & 1) * 8 + (lane & 7);
    const uint32_t b_koff = ((lane >> 3) & 1) * 16;
    const int cq = lane & 3;           // quad col group

    const int ntiles = (E + 15) / 16;                 // 16-edge tiles
    const int gw     = blockIdx.x * 8 + warp;         // global warp id
    const int nwarps = gridDim.x * 8;

    for (int t = gw; t < ntiles; t += nwarps) {
        const int e0 = t * 16;

        int e_ld = e0 + (lane & 15);
        int idxv = 0;
        if (e_ld < E) idxv = (lane < 16) ? eli[e_ld] : eli[(size_t)E + e_ld];

        #pragma unroll
        for (int jj = 0; jj < 4; jj++) {
            int id = jj * 32 + lane;        // 0..127 float4 slots
            int r = id >> 3, c4 = id & 7;
            float4 v = make_float4(0.f, 0.f, 0.f, 0.f);
            if (e0 + r < E)
                v = *(const float4*)(ea + (size_t)e0 * 32 + id * 4);
            uint2 uh, ul;
            split4(v, uh, ul);
            *(uint2*)(wAh + r * 40 + c4 * 4) = uh;
            *(uint2*)(wAl + r * 40 + c4 * 4) = ul;
        }
        __syncwarp();

        float acc[16][4];
        #pragma unroll
        for (int i = 0; i < 16; i++)
            #pragma unroll
            for (int j = 0; j < 4; j++) acc[i][j] = 0.f;

        #pragma unroll
        for (int kt = 0; kt < 2; kt++) {
            uint32_t ah[4], al[4];
            uint32_t aoff = a_row * 80 + kt * 32 + a_koff;
            ldsm4(ah, sbAh + aoff);
            ldsm4(al, sbAl + aoff);
            #pragma unroll
            for (int ntp = 0; ntp < 8; ntp++) {
                uint32_t boff = (ntp * 16 + b_rowi) * 80 + kt * 32 + b_koff;
                uint32_t bh[4], bl[4];
                ldsm4(bh, sbWh + boff);
                ldsm4(bl, sbWl + boff);
                mma_bf16(acc[2 * ntp],     ah, bh);
                mma_bf16(acc[2 * ntp],     ah, bl);
                mma_bf16(acc[2 * ntp],     al, bh);
                mma_bf16(acc[2 * ntp + 1], ah, bh + 2);
                mma_bf16(acc[2 * ntp + 1], ah, bl + 2);
                mma_bf16(acc[2 * ntp + 1], al, bh + 2);
            }
        }
        __syncwarp();

        #pragma unroll
        for (int i = 0; i < 2; i++) {
            int j    = (lane >> 2) + 8 * i;           // local edge 0..15
            int e    = e0 + j;
            int s    = __shfl_sync(0xffffffffu, idxv, j);
            int d    = __shfl_sync(0xffffffffu, idxv, j + 16);
            const __half2* pb = (const __half2*)(g_PQ + (size_t)s * 256) + cq;
            const __half2* qb = (const __half2*)(g_PQ + (size_t)d * 256 + 128) + cq;
            float part = 0.f;
            #pragma unroll
            for (int nt = 0; nt < 16; nt++) {
                float2 p  = __half22float2(__ldg(pb + nt * 4));
                float2 q  = __half22float2(__ldg(qb + nt * 4));
                float2 w2 = *(const float2*)(&sW2[nt * 8 + 2 * cq]);
                float h0 = fmaxf(acc[nt][2 * i]     + p.x + q.x, 0.f);
                float h1 = fmaxf(acc[nt][2 * i + 1] + p.y + q.y, 0.f);
                part = fmaf(h0, w2.x, fmaf(h1, w2.y, part));
            }
            part += __shfl_xor_sync(0xffffffffu, part, 1);
            part += __shfl_xor_sync(0xffffffffu, part, 2);
            if ((lane & 3) == 0 && e < E)
                out[e] = part + b2v;
        }
    }
}

// ---------------------------------------------------------------------------
extern "C" void kernel_launch(void* const* d_in, const int* in_sizes, int n_in,
                              void* d_out, int out_size) {
    const float* z   = (const float*)d_in[0];
    const int*   eli = (const int*)d_in[1];      // int32 (JAX canonicalized)
    const float* ea  = (const float*)d_in[2];
    const float* W1  = (const float*)d_in[3];
    const float* b1  = (const float*)d_in[4];
    const float* W2  = (const float*)d_in[5];
    const float* b2  = (const float*)d_in[6];
    float* out = (float*)d_out;

    int M = in_sizes[0] / NODE_DIM;   // 100000
    int E = out_size;                 // 1000000

    cudaFuncSetAttribute(gemm_tc_kernel,
                         cudaFuncAttributeMaxDynamicSharedMemorySize, GSMEM);

    conv_B_kernel<<<256, 256>>>(W1);

    int gblocks = (M + 63) / 64;
    gemm_tc_kernel<<<gblocks, 256, GSMEM>>>(z, b1, M);

    edge_kernel<<<296, 256>>>(eli, ea, W1, W2, b2, out, E);
}

// round 17
// speedup vs baseline: 1.6322x; 1.0776x over previous
#include <cuda_runtime.h>
#include <cuda_bf16.h>
#include <cuda_fp16.h>
#include <cstdint>

#define NODE_DIM 256
#define HIDDEN   128
#define MAX_NODES 100000

// ---------------- device scratch ----------------
__device__ __half        g_PQ [(size_t)MAX_NODES * 256];   // fp16 P(+b1)|Q per node
__device__ __nv_bfloat16 g_Bhi[256 * 256];                  // B[n][k] = W1ab[k][n]
__device__ __nv_bfloat16 g_Blo[256 * 256];

// ---------------- helpers ----------------
__device__ __forceinline__ uint32_t smem_u32(const void* p) {
    uint32_t a;
    asm("{ .reg .u64 t; cvta.to.shared.u64 t, %1; cvt.u32.u64 %0, t; }" : "=r"(a) : "l"(p));
    return a;
}
__device__ __forceinline__ void ldsm4(uint32_t* r, uint32_t addr) {
    asm volatile("ldmatrix.sync.aligned.m8n8.x4.shared.b16 {%0,%1,%2,%3}, [%4];"
        : "=r"(r[0]), "=r"(r[1]), "=r"(r[2]), "=r"(r[3]) : "r"(addr));
}
__device__ __forceinline__ void mma_bf16(float* d, const uint32_t* a, const uint32_t* b) {
    asm volatile("mma.sync.aligned.m16n8k16.row.col.f32.bf16.bf16.f32 "
        "{%0,%1,%2,%3}, {%4,%5,%6,%7}, {%8,%9}, {%0,%1,%2,%3};"
        : "+f"(d[0]), "+f"(d[1]), "+f"(d[2]), "+f"(d[3])
        : "r"(a[0]), "r"(a[1]), "r"(a[2]), "r"(a[3]), "r"(b[0]), "r"(b[1]));
}
__device__ __forceinline__ void cp_async16(uint32_t dst, const void* src) {
    asm volatile("cp.async.cg.shared.global [%0], [%1], 16;" :: "r"(dst), "l"(src));
}
#define CP_COMMIT() asm volatile("cp.async.commit_group;" ::: "memory")
#define CP_WAIT0()  asm volatile("cp.async.wait_group 0;" ::: "memory")

#define SW64S(o) ((o) ^ (((o) >> 3) & 0x30))

union BP4 { __nv_bfloat16 b[4]; uint2 u; };
__device__ __forceinline__ void split4(const float4& v, uint2& uh, uint2& ul) {
    float x[4] = {v.x, v.y, v.z, v.w};
    BP4 hi, lo;
    #pragma unroll
    for (int t = 0; t < 4; t++) {
        hi.b[t] = __float2bfloat16(x[t]);
        lo.b[t] = __float2bfloat16(x[t] - __bfloat162float(hi.b[t]));
    }
    uh = hi.u; ul = lo.u;
}

// ---------------------------------------------------------------------------
// conv_B: B[n][k] bf16 hi/lo.  n<128 -> W1[k][n]; n>=128 -> W1[256+k][n-128]
// ---------------------------------------------------------------------------
__global__ void conv_B_kernel(const float* __restrict__ W1) {
    int idx = blockIdx.x * blockDim.x + threadIdx.x;   // 0..65535
    int n = idx >> 8, k = idx & 255;
    float w = (n < HIDDEN) ? W1[(size_t)k * HIDDEN + n]
                           : W1[(size_t)(256 + k) * HIDDEN + (n - HIDDEN)];
    __nv_bfloat16 hi = __float2bfloat16(w);
    __nv_bfloat16 lo = __float2bfloat16(w - __bfloat162float(hi));
    g_Bhi[idx] = hi;
    g_Blo[idx] = lo;
}

// ---------------------------------------------------------------------------
// Phase 1 v3: PQ = z @ [W1a|W1b], bf16 3-term split, SOFTWARE-PIPELINED:
// double-buffered smem stages, cp.async B fetch, register-buffered A.
// CTA = 64 rows x 256 cols, 256 threads, 2 CTAs/SM. fp16 output, b1 folded.
// ---------------------------------------------------------------------------
#define SA_HI 0
#define SA_LO 4096
#define SB_HI 8192
#define SB_LO 24576
#define STAGE 40960
#define GSMEM (2 * STAGE)

__global__ __launch_bounds__(256, 2) void gemm_tc_kernel(
    const float* __restrict__ z, const float* __restrict__ b1, int M)
{
    extern __shared__ char smem[];
    const uint32_t sb = smem_u32(smem);
    const int tid  = threadIdx.x;
    const int warp = tid >> 5;
    const int lane = tid & 31;
    const int wr   = warp & 1;            // row group (32 rows)
    const int wc   = warp >> 1;           // col group (64 cols)
    const int m0   = blockIdx.x * 64;

    const uint32_t a_rbase = wr * 32 + ((lane >> 3) & 1) * 8 + (lane & 7);
    const uint32_t a_koff  = (lane >> 4) * 16;
    const uint32_t b_rowi  = ((lane >> 4) & 1) * 8 + (lane & 7);
    const uint32_t b_koff  = ((lane >> 3) & 1) * 16;

    const int lr = tid >> 2;              // 0..63 (A row)
    const int lc = tid & 3;               // 16B chunk in 64B row
    const bool arow_ok = (m0 + lr < M);
    const uint32_t a_sts = SW64S((uint32_t)(lr * 64 + lc * 16));

    // B cp.async per-thread indices (8 granules: 4 hi + 4 lo)
    // id = j*256 + tid; r = id>>2 (0..255), c = id&3
    uint32_t b_dst[4];
    const __nv_bfloat16* b_srch[4];
    const __nv_bfloat16* b_srcl[4];
    #pragma unroll
    for (int j = 0; j < 4; j++) {
        int id = j * 256 + tid;
        int r = id >> 2, c = id & 3;
        b_dst[j]  = SW64S((uint32_t)(r * 64 + c * 16));
        b_srch[j] = g_Bhi + (size_t)r * 256 + c * 8;
        b_srcl[j] = g_Blo + (size_t)r * 256 + c * 8;
    }

    float acc[2][8][4];
    #pragma unroll
    for (int mt = 0; mt < 2; mt++)
        #pragma unroll
        for (int i = 0; i < 8; i++)
            #pragma unroll
            for (int j = 0; j < 4; j++) acc[mt][i][j] = 0.f;

    float4 av0, av1;

    // ---- prologue: stage 0 ----
    {
        av0 = make_float4(0.f, 0.f, 0.f, 0.f); av1 = av0;
        if (arow_ok) {
            const float* zp = z + (size_t)(m0 + lr) * 256 + lc * 8;
            av0 = *(const float4*)zp;
            av1 = *(const float4*)(zp + 4);
        }
        #pragma unroll
        for (int j = 0; j < 4; j++) {
            cp_async16(sb + SB_HI + b_dst[j], b_srch[j]);
            cp_async16(sb + SB_LO + b_dst[j], b_srcl[j]);
        }
        CP_COMMIT();
        uint2 h0, l0, h1, l1;
        split4(av0, h0, l0);
        split4(av1, h1, l1);
        *(uint4*)(smem + SA_HI + a_sts) = make_uint4(h0.x, h0.y, h1.x, h1.y);
        *(uint4*)(smem + SA_LO + a_sts) = make_uint4(l0.x, l0.y, l1.x, l1.y);
        CP_WAIT0();
        __syncthreads();
    }

    #pragma unroll 1
    for (int ch = 0; ch < 8; ch++) {
        const uint32_t buf  = (uint32_t)(ch & 1) * STAGE;
        const uint32_t nbuf = buf ^ STAGE;

        // issue next stage's loads (A to regs, B via cp.async)
        if (ch < 7) {
            const int kc = (ch + 1) * 32;
            av0 = make_float4(0.f, 0.f, 0.f, 0.f); av1 = av0;
            if (arow_ok) {
                const float* zp = z + (size_t)(m0 + lr) * 256 + kc + lc * 8;
                av0 = *(const float4*)zp;
                av1 = *(const float4*)(zp + 4);
            }
            #pragma unroll
            for (int j = 0; j < 4; j++) {
                cp_async16(sb + nbuf + SB_HI + b_dst[j], b_srch[j] + kc);
                cp_async16(sb + nbuf + SB_LO + b_dst[j], b_srcl[j] + kc);
            }
            CP_COMMIT();
        }

        // MMAs on current stage
        #pragma unroll
        for (int kt = 0; kt < 2; kt++) {
            uint32_t ah[2][4], al[2][4];
            #pragma unroll
            for (int mt = 0; mt < 2; mt++) {
                uint32_t aoff = SW64S((a_rbase + mt * 16) * 64 + kt * 32 + a_koff);
                ldsm4(ah[mt], sb + buf + SA_HI + aoff);
                ldsm4(al[mt], sb + buf + SA_LO + aoff);
            }
            #pragma unroll
            for (int bg = 0; bg < 4; bg++) {
                uint32_t boff = SW64S((uint32_t)((wc * 64 + bg * 16 + b_rowi) * 64
                                                 + kt * 32 + b_koff));
                uint32_t bh[4], bl[4];
                ldsm4(bh, sb + buf + SB_HI + boff);
                ldsm4(bl, sb + buf + SB_LO + boff);
                #pragma unroll
                for (int mt = 0; mt < 2; mt++) {
                    mma_bf16(acc[mt][2 * bg],     ah[mt], bh);
                    mma_bf16(acc[mt][2 * bg],     ah[mt], bl);
                    mma_bf16(acc[mt][2 * bg],     al[mt], bh);
                    mma_bf16(acc[mt][2 * bg + 1], ah[mt], bh + 2);
                    mma_bf16(acc[mt][2 * bg + 1], ah[mt], bl + 2);
                    mma_bf16(acc[mt][2 * bg + 1], al[mt], bh + 2);
                }
            }
        }

        if (ch < 7) {
            uint2 h0, l0, h1, l1;
            split4(av0, h0, l0);
            split4(av1, h1, l1);
            char* base = smem + (size_t)(nbuf);
            *(uint4*)(base + SA_HI + a_sts) = make_uint4(h0.x, h0.y, h1.x, h1.y);
            *(uint4*)(base + SA_LO + a_sts) = make_uint4(l0.x, l0.y, l1.x, l1.y);
            CP_WAIT0();
            __syncthreads();
        }
    }

    // Epilogue: +b1 on P half (cols < 128), convert fp16, write g_PQ
    const int cbl = 2 * (lane & 3);
    #pragma unroll
    for (int mt = 0; mt < 2; mt++) {
        const int r0 = m0 + wr * 32 + mt * 16 + (lane >> 2);
        #pragma unroll
        for (int nn = 0; nn < 8; nn++) {
            int n0 = wc * 64 + nn * 8 + cbl;
            float2 bb = make_float2(0.f, 0.f);
            if (n0 < 128) bb = __ldg((const float2*)(b1 + n0));
            if (r0 < M)
                *(__half2*)(g_PQ + (size_t)r0 * 256 + n0) =
                    __floats2half2_rn(acc[mt][nn][0] + bb.x, acc[mt][nn][1] + bb.y);
            if (r0 + 8 < M)
                *(__half2*)(g_PQ + (size_t)(r0 + 8) * 256 + n0) =
                    __floats2half2_rn(acc[mt][nn][2] + bb.x, acc[mt][nn][3] + bb.y);
        }
    }
}

// ---------------------------------------------------------------------------
// Phase 2 (frozen at R15/R16): barrier-free warp-independent pipeline,
// fp16 P/Q gathers.
// ---------------------------------------------------------------------------
__global__ __launch_bounds__(256, 2) void edge_kernel(
    const int* __restrict__ eli, const float* __restrict__ ea,
    const float* __restrict__ W1, const float* __restrict__ W2,
    const float* __restrict__ b2, float* __restrict__ out, int E)
{
    __shared__ __align__(16) __nv_bfloat16 sAh[8 * 16 * 40];  // per-warp 16x40
    __shared__ __align__(16) __nv_bfloat16 sAl[8 * 16 * 40];
    __shared__ __align__(16) __nv_bfloat16 sWh[128 * 40];
    __shared__ __align__(16) __nv_bfloat16 sWl[128 * 40];
    __shared__ float sW2[128];

    const int tid  = threadIdx.x;
    const int warp = tid >> 5;
    const int lane = tid & 31;

    #pragma unroll
    for (int j = 0; j < 16; j++) {
        int id = j * 256 + tid;            // 0..4095
        int k = id >> 7, n = id & 127;
        float w = W1[(size_t)(512 + k) * HIDDEN + n];
        __nv_bfloat16 hi = __float2bfloat16(w);
        sWh[n * 40 + k] = hi;
        sWl[n * 40 + k] = __float2bfloat16(w - __bfloat162float(hi));
    }
    if (tid < 128) sW2[tid] = W2[tid];
    const float b2v = b2[0];
    __syncthreads();            // only barrier: sW/sW2 ready

    __nv_bfloat16* wAh = sAh + warp * 640;
    __nv_bfloat16* wAl = sAl + warp * 640;
    const uint32_t sbAh = smem_u32(wAh), sbAl = smem_u32(wAl);
    const uint32_t sbWh = smem_u32(sWh), sbWl = smem_u32(sWl);

    const uint32_t a_row  = ((lane >> 3) & 1) * 8 + (lane & 7);   // 0..15 local
    const uint32_t a_koff = (lane >> 4) * 16;
    const uint32_t b_rowi = ((lane >> 4) & 1) * 8 + (lane & 7);
    const uint32_t b_koff = ((lane >> 3) & 1) * 16;
    const int cq = lane & 3;           // quad col group

    const int ntiles = (E + 15) / 16;                 // 16-edge tiles
    const int gw     = blockIdx.x * 8 + warp;         // global warp id
    const int nwarps = gridDim.x * 8;

    for (int t = gw; t < ntiles; t += nwarps) {
        const int e0 = t * 16;

        int e_ld = e0 + (lane & 15);
        int idxv = 0;
        if (e_ld < E) idxv = (lane < 16) ? eli[e_ld] : eli[(size_t)E + e_ld];

        #pragma unroll
        for (int jj = 0; jj < 4; jj++) {
            int id = jj * 32 + lane;        // 0..127 float4 slots
            int r = id >> 3, c4 = id & 7;
            float4 v = make_float4(0.f, 0.f, 0.f, 0.f);
            if (e0 + r < E)
                v = *(const float4*)(ea + (size_t)e0 * 32 + id * 4);
            uint2 uh, ul;
            split4(v, uh, ul);
            *(uint2*)(wAh + r * 40 + c4 * 4) = uh;
            *(uint2*)(wAl + r * 40 + c4 * 4) = ul;
        }
        __syncwarp();

        float acc[16][4];
        #pragma unroll
        for (int i = 0; i < 16; i++)
            #pragma unroll
            for (int j = 0; j < 4; j++) acc[i][j] = 0.f;

        #pragma unroll
        for (int kt = 0; kt < 2; kt++) {
            uint32_t ah[4], al[4];
            uint32_t aoff = a_row * 80 + kt * 32 + a_koff;
            ldsm4(ah, sbAh + aoff);
            ldsm4(al, sbAl + aoff);
            #pragma unroll
            for (int ntp = 0; ntp < 8; ntp++) {
                uint32_t boff = (ntp * 16 + b_rowi) * 80 + kt * 32 + b_koff;
                uint32_t bh[4], bl[4];
                ldsm4(bh, sbWh + boff);
                ldsm4(bl, sbWl + boff);
                mma_bf16(acc[2 * ntp],     ah, bh);
                mma_bf16(acc[2 * ntp],     ah, bl);
                mma_bf16(acc[2 * ntp],     al, bh);
                mma_bf16(acc[2 * ntp + 1], ah, bh + 2);
                mma_bf16(acc[2 * ntp + 1], ah, bl + 2);
                mma_bf16(acc[2 * ntp + 1], al, bh + 2);
            }
        }
        __syncwarp();

        #pragma unroll
        for (int i = 0; i < 2; i++) {
            int j    = (lane >> 2) + 8 * i;           // local edge 0..15
            int e    = e0 + j;
            int s    = __shfl_sync(0xffffffffu, idxv, j);
            int d    = __shfl_sync(0xffffffffu, idxv, j + 16);
            const __half2* pb = (const __half2*)(g_PQ + (size_t)s * 256) + cq;
            const __half2* qb = (const __half2*)(g_PQ + (size_t)d * 256 + 128) + cq;
            float part = 0.f;
            #pragma unroll
            for (int nt = 0; nt < 16; nt++) {
                float2 p  = __half22float2(__ldg(pb + nt * 4));
                float2 q  = __half22float2(__ldg(qb + nt * 4));
                float2 w2 = *(const float2*)(&sW2[nt * 8 + 2 * cq]);
                float h0 = fmaxf(acc[nt][2 * i]     + p.x + q.x, 0.f);
                float h1 = fmaxf(acc[nt][2 * i + 1] + p.y + q.y, 0.f);
                part = fmaf(h0, w2.x, fmaf(h1, w2.y, part));
            }
            part += __shfl_xor_sync(0xffffffffu, part, 1);
            part += __shfl_xor_sync(0xffffffffu, part, 2);
            if ((lane & 3) == 0 && e < E)
                out[e] = part + b2v;
        }
    }
}

// ---------------------------------------------------------------------------
extern "C" void kernel_launch(void* const* d_in, const int* in_sizes, int n_in,
                              void* d_out, int out_size) {
    const float* z   = (const float*)d_in[0];
    const int*   eli = (const int*)d_in[1];      // int32 (JAX canonicalized)
    const float* ea  = (const float*)d_in[2];
    const float* W1  = (const float*)d_in[3];
    const float* b1  = (const float*)d_in[4];
    const float* W2  = (const float*)d_in[5];
    const float* b2  = (const float*)d_in[6];
    float* out = (float*)d_out;

    int M = in_sizes[0] / NODE_DIM;   // 100000
    int E = out_size;                 // 1000000

    cudaFuncSetAttribute(gemm_tc_kernel,
                         cudaFuncAttributeMaxDynamicSharedMemorySize, GSMEM);

    conv_B_kernel<<<256, 256>>>(W1);

    int gblocks = (M + 63) / 64;
    gemm_tc_kernel<<<gblocks, 256, GSMEM>>>(z, b1, M);

    edge_kernel<<<296, 256>>>(eli, ea, W1, W2, b2, out, E);
}